// round 5
// baseline (speedup 1.0000x reference)
#include <cuda_runtime.h>
#include <cuda_bf16.h>
#include <cstdint>

#define XB     32
#define XL     262144
#define FLEN   10001
#define NOUT   534288
#define LPAD   5120
#define XPLEN  272384
#define NT     80
#define NCTA   1044          // ceil(ceil(NOUT/128)/4)

#define ROWB   144           // smem row stride (bytes): conflict-free ldmatrix
#define REGB   (128 * ROWB)  // one operand region: 18432 B
#define STAGE  (4 * REGB)    // Ah | Al | Bh | Bl = 73728 B
#define SMEM_TOTAL (2 * STAGE)

__device__ __align__(256) __nv_bfloat16 g_xpad[2][XB][XPLEN];
__device__ __align__(256) __nv_bfloat16 g_W[2][NT][128 * 64];

__device__ __forceinline__ uint32_t smem_u32(const void* p) {
    uint32_t a;
    asm("{ .reg .u64 t; cvta.to.shared.u64 t, %1; cvt.u32.u64 %0, t; }" : "=r"(a) : "l"(p));
    return a;
}
__device__ __forceinline__ void cp16(uint32_t dst, const void* src) {
    asm volatile("cp.async.cg.shared.global [%0], [%1], 16;" :: "r"(dst), "l"(src));
}
__device__ __forceinline__ void ldsm4(uint32_t* r, uint32_t addr) {
    asm volatile("ldmatrix.sync.aligned.m8n8.x4.shared.b16 {%0,%1,%2,%3}, [%4];"
                 : "=r"(r[0]), "=r"(r[1]), "=r"(r[2]), "=r"(r[3]) : "r"(addr));
}
__device__ __forceinline__ void ldsm2(uint32_t* r, uint32_t addr) {
    asm volatile("ldmatrix.sync.aligned.m8n8.x2.shared.b16 {%0,%1}, [%2];"
                 : "=r"(r[0]), "=r"(r[1]) : "r"(addr));
}
__device__ __forceinline__ void mma16816(float* c, const uint32_t* a, const uint32_t* b) {
    asm volatile(
        "mma.sync.aligned.m16n8k16.row.col.f32.bf16.bf16.f32 "
        "{%0,%1,%2,%3}, {%4,%5,%6,%7}, {%8,%9}, {%0,%1,%2,%3};"
        : "+f"(c[0]), "+f"(c[1]), "+f"(c[2]), "+f"(c[3])
        : "r"(a[0]), "r"(a[1]), "r"(a[2]), "r"(a[3]), "r"(b[0]), "r"(b[1]));
}

// ---------------- prologue 1: pad + hi/lo bf16 split of x ----------------
__global__ void prep_x(const float* __restrict__ x) {
    int idx = blockIdx.x * blockDim.x + threadIdx.x;
    if (idx >= XB * XPLEN) return;
    int b = idx / XPLEN;
    int j = idx - b * XPLEN;
    int i = j - LPAD;
    float v = (i >= 0 && i < XL) ? x[(long)b * XL + i] : 0.0f;
    __nv_bfloat16 h = __float2bfloat16(v);
    float r = v - __bfloat162float(h);
    g_xpad[0][b][j] = h;
    g_xpad[1][b][j] = __float2bfloat16(r);
}

// ---------------- prologue 2: Toeplitz tiles (linear layout) ----------------
// A_t[r,kk] = w[128t + r - 2kk], r in [0,128), kk in [0,64)
__global__ void prep_w(const float* __restrict__ w) {
    int idx = blockIdx.x * blockDim.x + threadIdx.x;
    if (idx >= NT * 8192) return;
    int t  = idx >> 13;
    int r  = (idx >> 6) & 127;
    int kk = idx & 63;
    int widx = 128 * t + r - 2 * kk;
    float v = (widx >= 0 && widx < FLEN) ? w[widx] : 0.0f;
    __nv_bfloat16 h = __float2bfloat16(v);
    float rr = v - __bfloat162float(h);
    g_W[0][t][r * 64 + kk] = h;
    g_W[1][t][r * 64 + kk] = __float2bfloat16(rr);
}

// ---------------- prefetch one K-stage into smem ----------------
__device__ __forceinline__ void prefetch_stage(uint32_t sb, int t, int m0, int tid) {
    uint32_t st = sb + (t & 1) * STAGE;
    const char* wh = (const char*)&g_W[0][t][0];
    const char* wl = (const char*)&g_W[1][t][0];
    #pragma unroll
    for (int q = tid; q < 1024; q += 256) {
        int r = q >> 3, c = q & 7;
        uint32_t d = st + r * ROWB + c * 16;
        cp16(d,        wh + q * 16);
        cp16(d + REGB, wl + q * 16);
    }
    int off0 = LPAD + 64 * (m0 - t);
    #pragma unroll
    for (int q = tid; q < 1024; q += 256) {
        int r = q >> 3, c = q & 7;
        int ms = r >> 5, b = r & 31;
        int e = off0 + ms * 64 + c * 8;
        uint32_t d = st + 2 * REGB + r * ROWB + c * 16;
        cp16(d,        &g_xpad[0][b][e]);
        cp16(d + REGB, &g_xpad[1][b][e]);
    }
    asm volatile("cp.async.commit_group;" ::: "memory");
}

// ---------------- main GEMM (classic mma.sync, bf16 3-split) ----------------
__global__ void __launch_bounds__(256, 1) conv_main(float* __restrict__ out) {
    extern __shared__ __align__(128) char smem[];
    uint32_t sb = smem_u32(smem);
    int tid = threadIdx.x, wid = tid >> 5, lane = tid & 31;
    int m0 = blockIdx.x * 4;
    int warp_m = wid >> 2;    // 0..1 : rows [warp_m*64, +64)
    int warp_n = wid & 3;     // 0..3 : cols [warp_n*32, +32)  (warp_n == msub)

    float acc[4][4][4];
    #pragma unroll
    for (int mi = 0; mi < 4; mi++)
        #pragma unroll
        for (int ni = 0; ni < 4; ni++)
            #pragma unroll
            for (int j = 0; j < 4; j++) acc[mi][ni][j] = 0.0f;

    // per-lane ldmatrix address components
    int a_row = lane & 15;
    int a_k8  = (lane >> 4) << 3;         // 0 or 8 (k halves for x4)
    int b_row = lane & 7;
    int b_k8  = ((lane >> 3) & 1) << 3;   // 0 or 8 (k halves for x2)

    prefetch_stage(sb, 0, m0, tid);

    for (int t = 0; t < NT; t++) {
        if (t + 1 < NT) {
            prefetch_stage(sb, t + 1, m0, tid);
            asm volatile("cp.async.wait_group 1;" ::: "memory");
        } else {
            asm volatile("cp.async.wait_group 0;" ::: "memory");
        }
        __syncthreads();

        uint32_t st = sb + (t & 1) * STAGE;
        uint32_t Ah = st, Al = st + REGB, Bh = st + 2 * REGB, Bl = st + 3 * REGB;

        #pragma unroll
        for (int ks = 0; ks < 4; ks++) {
            uint32_t ah[4][4], al[4][4];
            #pragma unroll
            for (int mi = 0; mi < 4; mi++) {
                uint32_t ao = (uint32_t)((warp_m * 64 + mi * 16 + a_row) * ROWB +
                                         (ks * 16 + a_k8) * 2);
                ldsm4(ah[mi], Ah + ao);
                ldsm4(al[mi], Al + ao);
            }
            #pragma unroll
            for (int ni = 0; ni < 4; ni++) {
                uint32_t bo = (uint32_t)((warp_n * 32 + ni * 8 + b_row) * ROWB +
                                         (ks * 16 + b_k8) * 2);
                uint32_t bhf[2], blf[2];
                ldsm2(bhf, Bh + bo);
                ldsm2(blf, Bl + bo);
                #pragma unroll
                for (int mi = 0; mi < 4; mi++) {
                    mma16816(acc[mi][ni], ah[mi], bhf);
                    mma16816(acc[mi][ni], ah[mi], blf);
                    mma16816(acc[mi][ni], al[mi], bhf);
                }
            }
        }
        __syncthreads();
    }

    // ---------------- epilogue: D[r, c] -> out[b, 128*(m0+warp_n) + r] ----------------
    long nbase = 128L * (m0 + warp_n);
    #pragma unroll
    for (int mi = 0; mi < 4; mi++) {
        long r0 = warp_m * 64 + mi * 16 + (lane >> 2);
        #pragma unroll
        for (int ni = 0; ni < 4; ni++) {
            int b = ni * 8 + (lane & 3) * 2;
            long n0 = nbase + r0;
            if (n0 < NOUT) {
                out[(long)b * NOUT + n0]       = acc[mi][ni][0];
                out[(long)(b + 1) * NOUT + n0] = acc[mi][ni][1];
            }
            long n1 = n0 + 8;
            if (n1 < NOUT) {
                out[(long)b * NOUT + n1]       = acc[mi][ni][2];
                out[(long)(b + 1) * NOUT + n1] = acc[mi][ni][3];
            }
        }
    }
}

extern "C" void kernel_launch(void* const* d_in, const int* in_sizes, int n_in,
                              void* d_out, int out_size) {
    const float* x = (const float*)d_in[0];
    const float* w = (const float*)d_in[1];
    float* out = (float*)d_out;
    (void)in_sizes; (void)n_in; (void)out_size;

    cudaFuncSetAttribute(conv_main, cudaFuncAttributeMaxDynamicSharedMemorySize, SMEM_TOTAL);

    int nx = XB * XPLEN;
    prep_x<<<(nx + 255) / 256, 256>>>(x);
    int nw = NT * 8192;
    prep_w<<<(nw + 255) / 256, 256>>>(w);
    conv_main<<<NCTA, 256, SMEM_TOTAL>>>(out);
}

// round 6
// speedup vs baseline: 2.8124x; 2.8124x over previous
#include <cuda_runtime.h>
#include <cuda_fp16.h>
#include <cstdint>

#define XB     32
#define XL     262144
#define FLEN   10001
#define NOUT   534288
#define LPAD   5120
#define XPLEN  272384
#define NT     80
#define NCTA   1044          // ceil(ceil(NOUT/128)/4)

#define ROWB   144           // smem row stride (bytes): conflict-free ldmatrix
#define REGB   (128 * ROWB)  // one operand region: 18432 B
#define STAGE  (2 * REGB)    // A | B = 36864 B
#define SMEM_TOTAL (2 * STAGE)

__device__ __align__(256) __half g_xpad[XB][XPLEN];
__device__ __align__(256) __half g_W[NT][128 * 64];

__device__ __forceinline__ uint32_t smem_u32(const void* p) {
    uint32_t a;
    asm("{ .reg .u64 t; cvta.to.shared.u64 t, %1; cvt.u32.u64 %0, t; }" : "=r"(a) : "l"(p));
    return a;
}
__device__ __forceinline__ void cp16(uint32_t dst, const void* src) {
    asm volatile("cp.async.cg.shared.global [%0], [%1], 16;" :: "r"(dst), "l"(src));
}
__device__ __forceinline__ void ldsm4(uint32_t* r, uint32_t addr) {
    asm volatile("ldmatrix.sync.aligned.m8n8.x4.shared.b16 {%0,%1,%2,%3}, [%4];"
                 : "=r"(r[0]), "=r"(r[1]), "=r"(r[2]), "=r"(r[3]) : "r"(addr));
}
__device__ __forceinline__ void mma16816(float* c, const uint32_t* a, const uint32_t* b) {
    asm volatile(
        "mma.sync.aligned.m16n8k16.row.col.f32.f16.f16.f32 "
        "{%0,%1,%2,%3}, {%4,%5,%6,%7}, {%8,%9}, {%0,%1,%2,%3};"
        : "+f"(c[0]), "+f"(c[1]), "+f"(c[2]), "+f"(c[3])
        : "r"(a[0]), "r"(a[1]), "r"(a[2]), "r"(a[3]), "r"(b[0]), "r"(b[1]));
}

// ---------------- prologue 1: pad x, convert to fp16 ----------------
__global__ void prep_x(const float* __restrict__ x) {
    int idx = blockIdx.x * blockDim.x + threadIdx.x;
    if (idx >= XB * XPLEN) return;
    int b = idx / XPLEN;
    int j = idx - b * XPLEN;
    int i = j - LPAD;
    float v = (i >= 0 && i < XL) ? x[(long)b * XL + i] : 0.0f;
    g_xpad[b][j] = __float2half(v);
}

// ---------------- prologue 2: Toeplitz tiles (linear layout) ----------------
// A_t[r,kk] = w[128t + r - 2kk], r in [0,128), kk in [0,64)
__global__ void prep_w(const float* __restrict__ w) {
    int idx = blockIdx.x * blockDim.x + threadIdx.x;
    if (idx >= NT * 8192) return;
    int t  = idx >> 13;
    int r  = (idx >> 6) & 127;
    int kk = idx & 63;
    int widx = 128 * t + r - 2 * kk;
    float v = (widx >= 0 && widx < FLEN) ? w[widx] : 0.0f;
    g_W[t][r * 64 + kk] = __float2half(v);
}

// ---------------- prefetch one K-stage into smem ----------------
__device__ __forceinline__ void prefetch_stage(uint32_t sb, int t, int m0, int tid) {
    uint32_t st = sb + (t & 1) * STAGE;
    const char* wsrc = (const char*)&g_W[t][0];
    #pragma unroll
    for (int q = tid; q < 1024; q += 256) {
        int r = q >> 3, c = q & 7;
        cp16(st + r * ROWB + c * 16, wsrc + q * 16);
    }
    int off0 = LPAD + 64 * (m0 - t);
    #pragma unroll
    for (int q = tid; q < 1024; q += 256) {
        int r = q >> 3, c = q & 7;
        int ms = r >> 5, b = r & 31;
        int e = off0 + ms * 64 + c * 8;
        cp16(st + REGB + r * ROWB + c * 16, &g_xpad[b][e]);
    }
    asm volatile("cp.async.commit_group;" ::: "memory");
}

// ---------------- main GEMM (mma.sync fp16, single term) ----------------
__global__ void __launch_bounds__(256, 2) conv_main(float* __restrict__ out) {
    extern __shared__ __align__(128) char smem[];
    uint32_t sb = smem_u32(smem);
    int tid = threadIdx.x, wid = tid >> 5, lane = tid & 31;
    int m0 = blockIdx.x * 4;
    int warp_m = wid >> 2;    // 0..1 : rows [warp_m*64, +64)
    int warp_n = wid & 3;     // 0..3 : cols [warp_n*32, +32)  (warp_n == msub)

    float acc[4][4][4];
    #pragma unroll
    for (int mi = 0; mi < 4; mi++)
        #pragma unroll
        for (int ni = 0; ni < 4; ni++)
            #pragma unroll
            for (int j = 0; j < 4; j++) acc[mi][ni][j] = 0.0f;

    // ldmatrix lane address components
    int a_row = lane & 15;
    int a_k8  = (lane >> 4) << 3;          // 0/8
    int b_mat = lane >> 3;                 // 0..3
    int b_sub = b_mat >> 1;                // n-subtile (0/1)
    int b_k8  = (b_mat & 1) << 3;          // k-half (0/8)
    int b_row = lane & 7;

    prefetch_stage(sb, 0, m0, tid);

    for (int t = 0; t < NT; t++) {
        if (t + 1 < NT) {
            prefetch_stage(sb, t + 1, m0, tid);
            asm volatile("cp.async.wait_group 1;" ::: "memory");
        } else {
            asm volatile("cp.async.wait_group 0;" ::: "memory");
        }
        __syncthreads();

        uint32_t st = sb + (t & 1) * STAGE;
        uint32_t A = st, B = st + REGB;

        #pragma unroll
        for (int ks = 0; ks < 4; ks++) {
            uint32_t ah[4][4];
            #pragma unroll
            for (int mi = 0; mi < 4; mi++) {
                uint32_t ao = (uint32_t)((warp_m * 64 + mi * 16 + a_row) * ROWB +
                                         (ks * 16 + a_k8) * 2);
                ldsm4(ah[mi], A + ao);
            }
            #pragma unroll
            for (int ni2 = 0; ni2 < 2; ni2++) {
                uint32_t bf[4];
                uint32_t bo = (uint32_t)((warp_n * 32 + ni2 * 16 + b_sub * 8 + b_row) * ROWB +
                                         (ks * 16 + b_k8) * 2);
                ldsm4(bf, B + bo);
                #pragma unroll
                for (int mi = 0; mi < 4; mi++) {
                    mma16816(acc[mi][ni2 * 2 + 0], ah[mi], bf);
                    mma16816(acc[mi][ni2 * 2 + 1], ah[mi], bf + 2);
                }
            }
        }
        __syncthreads();
    }

    // ---------------- epilogue: D[r, c] -> out[b, 128*(m0+warp_n) + r] ----------------
    long nbase = 128L * (m0 + warp_n);
    #pragma unroll
    for (int mi = 0; mi < 4; mi++) {
        long r0 = warp_m * 64 + mi * 16 + (lane >> 2);
        #pragma unroll
        for (int ni = 0; ni < 4; ni++) {
            int b = ni * 8 + (lane & 3) * 2;
            long n0 = nbase + r0;
            if (n0 < NOUT) {
                out[(long)b * NOUT + n0]       = acc[mi][ni][0];
                out[(long)(b + 1) * NOUT + n0] = acc[mi][ni][1];
            }
            long n1 = n0 + 8;
            if (n1 < NOUT) {
                out[(long)b * NOUT + n1]       = acc[mi][ni][2];
                out[(long)(b + 1) * NOUT + n1] = acc[mi][ni][3];
            }
        }
    }
}

extern "C" void kernel_launch(void* const* d_in, const int* in_sizes, int n_in,
                              void* d_out, int out_size) {
    const float* x = (const float*)d_in[0];
    const float* w = (const float*)d_in[1];
    float* out = (float*)d_out;
    (void)in_sizes; (void)n_in; (void)out_size;

    cudaFuncSetAttribute(conv_main, cudaFuncAttributeMaxDynamicSharedMemorySize, SMEM_TOTAL);

    int nx = XB * XPLEN;
    prep_x<<<(nx + 255) / 256, 256>>>(x);
    int nw = NT * 8192;
    prep_w<<<(nw + 255) / 256, 256>>>(w);
    conv_main<<<NCTA, 256, SMEM_TOTAL>>>(out);
}